// round 10
// baseline (speedup 1.0000x reference)
#include <cuda_runtime.h>
#include <cuda_bf16.h>
#include <math.h>
#include <stdint.h>

#define QL   512
#define BSZ  8
#define HID  1024
#define NH   16
#define HD   64
#define PL   1024
#define IB   (QL*BSZ)
#define JBR  (PL*BSZ)
#define BNH  (BSZ*NH)
#define QKVW 3072
#define SCALEF 0.125f
#define BIGF   1e30f

// -------- fp32 scratch --------
__device__ float g_QKV[IB*QKVW];    // fused Q|K|V projections [4096][3072]
__device__ float g_KR[JBR*HID];
__device__ float g_PR[IB*HID];
__device__ float g_EF1[IB*NH*2];
__device__ float g_BW[BNH*QL];
__device__ float g_BR[BNH*PL];

// -------- bf16 split scratch --------
__device__ __nv_bfloat16 g_HA0[IB*HID],  g_HA1[IB*HID];
__device__ __nv_bfloat16 g_PA0[JBR*HID], g_PA1[JBR*HID];
__device__ __nv_bfloat16 g_AOs0[IB*HID], g_AOs1[IB*HID];
__device__ __nv_bfloat16 g_WB0[5*HID*HID], g_WB1[5*HID*HID];

// ============================ helpers ============================
__device__ __forceinline__ uint32_t smem_u32(const void* p) {
    uint32_t a;
    asm("{ .reg .u64 t; cvta.to.shared.u64 t, %1; cvt.u32.u64 %0, t; }"
        : "=r"(a) : "l"(p));
    return a;
}
#define SWZ(off) ((off) ^ (((off) >> 3) & 0x70))

__device__ __forceinline__ void ldsm_x4(uint32_t* r, uint32_t addr) {
    asm volatile("ldmatrix.sync.aligned.m8n8.x4.shared.b16 {%0,%1,%2,%3}, [%4];"
        : "=r"(r[0]), "=r"(r[1]), "=r"(r[2]), "=r"(r[3]) : "r"(addr));
}
__device__ __forceinline__ void ldsm_x2(uint32_t* r, uint32_t addr) {
    asm volatile("ldmatrix.sync.aligned.m8n8.x2.shared.b16 {%0,%1}, [%2];"
        : "=r"(r[0]), "=r"(r[1]) : "r"(addr));
}
__device__ __forceinline__ void mma_bf16(float* d, const uint32_t* a, const uint32_t* b) {
    asm volatile("mma.sync.aligned.m16n8k16.row.col.f32.bf16.bf16.f32 "
        "{%0,%1,%2,%3}, {%4,%5,%6,%7}, {%8,%9}, {%0,%1,%2,%3};"
        : "+f"(d[0]), "+f"(d[1]), "+f"(d[2]), "+f"(d[3])
        : "r"(a[0]), "r"(a[1]), "r"(a[2]), "r"(a[3]), "r"(b[0]), "r"(b[1]));
}
__device__ __forceinline__ void split2f(float v, __nv_bfloat16& a0, __nv_bfloat16& a1) {
    a0 = __float2bfloat16_rn(v);
    a1 = __float2bfloat16_rn(v - __bfloat162float(a0));
}
__device__ __forceinline__ uint32_t bpack(__nv_bfloat16 lo, __nv_bfloat16 hi) {
    __nv_bfloat162 t = __halves2bfloat162(lo, hi);
    return *(uint32_t*)&t;
}

// ============================ split kernels ============================
__global__ void split2_kernel(const float* __restrict__ X,
    __nv_bfloat16* __restrict__ S0, __nv_bfloat16* __restrict__ S1, int n4)
{
    int i = blockIdx.x * blockDim.x + threadIdx.x;
    if (i >= n4) return;
    float4 v = ((const float4*)X)[i];
    __nv_bfloat16 a[4], b[4];
    split2f(v.x, a[0], b[0]);
    split2f(v.y, a[1], b[1]);
    split2f(v.z, a[2], b[2]);
    split2f(v.w, a[3], b[3]);
    uint32_t* p0 = (uint32_t*)S0;
    uint32_t* p1 = (uint32_t*)S1;
    p0[2*i]   = bpack(a[0], a[1]);
    p0[2*i+1] = bpack(a[2], a[3]);
    p1[2*i]   = bpack(b[0], b[1]);
    p1[2*i+1] = bpack(b[2], b[3]);
}

__global__ void tsplit2_kernel(const float* __restrict__ W,
    __nv_bfloat16* __restrict__ T0, __nv_bfloat16* __restrict__ T1)
{
    __shared__ float t[32][33];
    const int n0 = blockIdx.x * 32, k0 = blockIdx.y * 32;
    const int tx = threadIdx.x, ty = threadIdx.y;
    for (int r = ty; r < 32; r += 8)
        t[r][tx] = W[(size_t)(k0 + r) * HID + n0 + tx];
    __syncthreads();
    for (int r = ty; r < 32; r += 8) {
        float v = t[tx][r];
        __nv_bfloat16 a, b; split2f(v, a, b);
        size_t o = (size_t)(n0 + r) * HID + k0 + tx;
        T0[o] = a; T1[o] = b;
    }
}

// ============================ HMMA GEMM (known-good) ============================
#define GEMM_SMEM 65536

__global__ __launch_bounds__(256, 2) void gemm_mma(
    const __nv_bfloat16* __restrict__ A0, const __nv_bfloat16* __restrict__ A1,
    const __nv_bfloat16* __restrict__ B0, const __nv_bfloat16* __restrict__ B1,
    float* __restrict__ C, int M, int N, int K)
{
    extern __shared__ char sm[];
    const uint32_t su = smem_u32(sm);
    const int tid = threadIdx.x, lane = tid & 31, wid = tid >> 5;
    const int wm = (wid >> 2) * 64, wn = (wid & 3) * 32;
    const int m0 = blockIdx.y * 128, n0 = blockIdx.x * 128;

    float acc[4][4][4];
#pragma unroll
    for (int mi = 0; mi < 4; ++mi)
#pragma unroll
        for (int ni = 0; ni < 4; ++ni)
#pragma unroll
            for (int q = 0; q < 4; ++q) acc[mi][ni][q] = 0.f;

    const __nv_bfloat16* Ap[2] = {A0, A1};
    const __nv_bfloat16* Bp[2] = {B0, B1};
    const int a_row = lane & 15, a_kb = (lane >> 4) * 16;
    const int b_row = lane & 7,  b_kb = ((lane >> 3) & 1) * 16;

    for (int k0 = 0; k0 < K; k0 += 64) {
        __syncthreads();
#pragma unroll
        for (int s = 0; s < 2; ++s) {
            const char* ag = (const char*)(Ap[s] + (size_t)m0 * K + k0);
            const char* bg = (const char*)(Bp[s] + (size_t)n0 * K + k0);
            char* at = sm + s * 16384;
            char* bt = sm + 32768 + s * 16384;
#pragma unroll
            for (int i = 0; i < 4; ++i) {
                const int off = (tid + i * 256) * 16;
                const int row = off >> 7, cb = off & 127;
                const size_t g = (size_t)row * K * 2 + cb;
                *(uint4*)(at + SWZ(off)) = *(const uint4*)(ag + g);
                *(uint4*)(bt + SWZ(off)) = *(const uint4*)(bg + g);
            }
        }
        __syncthreads();

        const int asel[3] = {0, 0, 1};
        const int bsel[3] = {0, 1, 0};
#pragma unroll
        for (int t = 0; t < 3; ++t) {
            const uint32_t At = su + asel[t] * 16384;
            const uint32_t Bt = su + 32768 + bsel[t] * 16384;
#pragma unroll
            for (int ks = 0; ks < 4; ++ks) {
                uint32_t af[4][4], bf[4][2];
#pragma unroll
                for (int mi = 0; mi < 4; ++mi) {
                    const int row = wm + mi * 16 + a_row;
                    const int off = row * 128 + ks * 32 + a_kb;
                    ldsm_x4(af[mi], At + SWZ(off));
                }
#pragma unroll
                for (int ni = 0; ni < 4; ++ni) {
                    const int row = wn + ni * 8 + b_row;
                    const int off = row * 128 + ks * 32 + b_kb;
                    ldsm_x2(bf[ni], Bt + SWZ(off));
                }
#pragma unroll
                for (int mi = 0; mi < 4; ++mi)
#pragma unroll
                    for (int ni = 0; ni < 4; ++ni)
                        mma_bf16(acc[mi][ni], af[mi], bf[ni]);
            }
        }
    }

    const int er = lane >> 2, ec = (lane & 3) * 2;
#pragma unroll
    for (int mi = 0; mi < 4; ++mi) {
#pragma unroll
        for (int ni = 0; ni < 4; ++ni) {
            const int row = m0 + wm + mi * 16 + er;
            const int col = n0 + wn + ni * 8 + ec;
            float2 v0 = {acc[mi][ni][0], acc[mi][ni][1]};
            float2 v1 = {acc[mi][ni][2], acc[mi][ni][3]};
            *(float2*)(C + (size_t)row * N + col)       = v0;
            *(float2*)(C + (size_t)(row + 8) * N + col) = v1;
        }
    }
}

// ============================ small precompute kernels ============================
__global__ void ef1_kernel(const float* __restrict__ QKV, const float* __restrict__ rsb,
                           const float* __restrict__ segm, float* __restrict__ EF1)
{
    int w = (blockIdx.x * blockDim.x + threadIdx.x) >> 5;
    int lane = threadIdx.x & 31;
    int n = w & 15, ib = w >> 4;
    const float* qp = QKV + (size_t)ib * QKVW + n * 64;
    const float* bp = rsb + n * 64;
    float q0 = qp[lane] + bp[lane];
    float q1 = qp[lane + 32] + bp[lane + 32];
    float s0 = q0 * segm[n*64 + lane]        + q1 * segm[n*64 + lane + 32];
    float s1 = q0 * segm[1024 + n*64 + lane] + q1 * segm[1024 + n*64 + lane + 32];
#pragma unroll
    for (int o = 16; o; o >>= 1) {
        s0 += __shfl_xor_sync(0xffffffffu, s0, o);
        s1 += __shfl_xor_sync(0xffffffffu, s1, o);
    }
    if (lane == 0) { EF1[w*2] = s0; EF1[w*2 + 1] = s1; }
}

// OUT[(b*16+n)*JLEN + j] = bias[n]·X[(j*B+b)*stride + coloff + n*64 ...]
__global__ void rowbias_kernel(const float* __restrict__ X, int stride, int coloff,
                               const float* __restrict__ bias,
                               float* __restrict__ OUT, int JLEN)
{
    int w = (blockIdx.x * blockDim.x + threadIdx.x) >> 5;
    int lane = threadIdx.x & 31;
    int n = w & 15, rem = w >> 4;
    int b = rem & 7, j = rem >> 3;
    const float* xp = X + (size_t)(j * BSZ + b) * stride + coloff + n * 64;
    float v = xp[lane] * bias[n*64 + lane] + xp[lane + 32] * bias[n*64 + lane + 32];
#pragma unroll
    for (int o = 16; o; o >>= 1) v += __shfl_xor_sync(0xffffffffu, v, o);
    if (lane == 0) OUT[(size_t)(b * 16 + n) * JLEN + j] = v;
}

// ============================ fused flash attention (i-tile 32, occ 2) ============================
// One CTA per (i-tile of 32, b, n). 8 j-chunks of 64. Band = 95 rows (+1 pad).
#define SA_Q0   0        // 32x64 bf16 (128B rows)
#define SA_Q1   4096
#define SA_K0   8192     // 64x64 bf16
#define SA_K1   16384
#define SA_R0   24576    // 96x64 bf16
#define SA_R1   36864
#define SA_SB   49152    // bd' fp32 [32][100]
#define SA_SC   61952    // score/P fp32 [32][68]
#define SA_VC   70656    // V chunk fp32 [64][68]
#define SA_RM   88064    // rowm [32]
#define SA_RS   88192    // rows [32]
#define SA_RF   88320    // rowf [32]
#define SA_BW   88448    // Bw [64]
#define SA_BR   88704    // Br [95] (+pad)
#define ATTN_SMEM 89088

__global__ __launch_bounds__(256, 2) void attn_kernel(
    const float* __restrict__ QKV, const float* __restrict__ KR,
    const float* __restrict__ EF1, const float* __restrict__ BW,
    const float* __restrict__ BR, const float* __restrict__ seg,
    const float* __restrict__ mask,
    __nv_bfloat16* __restrict__ AOs0, __nv_bfloat16* __restrict__ AOs1)
{
    extern __shared__ char sm[];
    const uint32_t su = smem_u32(sm);
    float* Sb = (float*)(sm + SA_SB);
    float* Sc = (float*)(sm + SA_SC);
    float* Vc = (float*)(sm + SA_VC);
    float* rowm = (float*)(sm + SA_RM);
    float* rows = (float*)(sm + SA_RS);
    float* rowf = (float*)(sm + SA_RF);
    float* Bws  = (float*)(sm + SA_BW);
    float* Brs  = (float*)(sm + SA_BR);

    const int tid = threadIdx.x, lane = tid & 31, wid = tid >> 5;
    const int i0 = blockIdx.x * 32;
    const int bz = blockIdx.y;            // b*16+n
    const int b = bz >> 4, n = bz & 15;
    const int wy = wid >> 2, wx = wid & 3;
    const int ty = tid >> 4, tx = tid & 15;

    // ---- load Q tile (split) : 32 rows, 8 floats/thread ----
    {
        const int il = tid >> 3, d0 = (tid & 7) * 8;
        const float* qp = QKV + (size_t)((i0 + il) * BSZ + b) * QKVW + n * 64 + d0;
        char* q0t = sm + SA_Q0;
        char* q1t = sm + SA_Q1;
#pragma unroll
        for (int u = 0; u < 2; ++u) {
            float4 v = *(const float4*)(qp + u * 4);
            __nv_bfloat16 a[4], c[4];
            split2f(v.x, a[0], c[0]); split2f(v.y, a[1], c[1]);
            split2f(v.z, a[2], c[2]); split2f(v.w, a[3], c[3]);
            const int off = il * 128 + (d0 + u * 4) * 2;
            *(uint32_t*)(q0t + SWZ(off))     = bpack(a[0], a[1]);
            *(uint32_t*)(q0t + SWZ(off + 4)) = bpack(a[2], a[3]);
            *(uint32_t*)(q1t + SWZ(off))     = bpack(c[0], c[1]);
            *(uint32_t*)(q1t + SWZ(off + 4)) = bpack(c[2], c[3]);
        }
    }
    if (tid < 32) { rowm[tid] = -BIGF; rows[tid] = 0.f; }

    float efx[2], efy[2];
#pragma unroll
    for (int m = 0; m < 2; ++m) {
        const int i = i0 + ty * 2 + m;
        const float2 ef = *(const float2*)&EF1[((size_t)(i * BSZ + b) * 16 + n) * 2];
        efx[m] = ef.x; efy[m] = ef.y;
    }

    float O[2][4];
#pragma unroll
    for (int m = 0; m < 2; ++m)
#pragma unroll
        for (int q = 0; q < 4; ++q) O[m][q] = 0.f;

    const int a_row = lane & 15, a_kb = (lane >> 4) * 16;
    const int b_row = lane & 7,  b_kb = ((lane >> 3) & 1) * 16;

    for (int jc0 = 0; jc0 < QL; jc0 += 64) {
        const int gb = jc0 - i0 + 481;    // first KR band row (global), in [1, 929]
        __syncthreads();

        // ---- load K chunk (split) + V chunk ----
        {
            const int jl = tid >> 2, d0 = (tid & 3) * 16;
            const float* kp = QKV + (size_t)((jc0 + jl) * BSZ + b) * QKVW + 1024 + n * 64 + d0;
            char* k0t = sm + SA_K0;
            char* k1t = sm + SA_K1;
#pragma unroll
            for (int u = 0; u < 4; ++u) {
                float4 v = *(const float4*)(kp + u * 4);
                __nv_bfloat16 a[4], c[4];
                split2f(v.x, a[0], c[0]); split2f(v.y, a[1], c[1]);
                split2f(v.z, a[2], c[2]); split2f(v.w, a[3], c[3]);
                const int off = jl * 128 + (d0 + u * 4) * 2;
                *(uint32_t*)(k0t + SWZ(off))     = bpack(a[0], a[1]);
                *(uint32_t*)(k0t + SWZ(off + 4)) = bpack(a[2], a[3]);
                *(uint32_t*)(k1t + SWZ(off))     = bpack(c[0], c[1]);
                *(uint32_t*)(k1t + SWZ(off + 4)) = bpack(c[2], c[3]);
            }
            const float* vp = QKV + (size_t)((jc0 + jl) * BSZ + b) * QKVW + 2048 + n * 64 + d0;
#pragma unroll
            for (int u = 0; u < 4; ++u) {
                float4 v = *(const float4*)(vp + u * 4);
                *(float4*)&Vc[jl * 68 + d0 + u * 4] = v;
            }
        }
        // ---- load KR band 95 rows (split; row 95 pad zero) ----
        {
            const int t = tid >> 1, d0 = (tid & 1) * 32;
            char* r0t = sm + SA_R0;
            char* r1t = sm + SA_R1;
            if (t < 95) {
                const float* rp = KR + (size_t)((gb + t) * BSZ + b) * HID + n * 64 + d0;
#pragma unroll
                for (int u = 0; u < 8; ++u) {
                    float4 v = *(const float4*)(rp + u * 4);
                    __nv_bfloat16 a[4], c[4];
                    split2f(v.x, a[0], c[0]); split2f(v.y, a[1], c[1]);
                    split2f(v.z, a[2], c[2]); split2f(v.w, a[3], c[3]);
                    const int off = t * 128 + (d0 + u * 4) * 2;
                    *(uint32_t*)(r0t + SWZ(off))     = bpack(a[0], a[1]);
                    *(uint32_t*)(r0t + SWZ(off + 4)) = bpack(a[2], a[3]);
                    *(uint32_t*)(r1t + SWZ(off))     = bpack(c[0], c[1]);
                    *(uint32_t*)(r1t + SWZ(off + 4)) = bpack(c[2], c[3]);
                }
            } else if (t == 95) {
#pragma unroll
                for (int u = 0; u < 8; ++u) {
                    const int off = t * 128 + (d0 + u * 4) * 2;
                    *(uint32_t*)(r0t + SWZ(off))     = 0u;
                    *(uint32_t*)(r0t + SWZ(off + 4)) = 0u;
                    *(uint32_t*)(r1t + SWZ(off))     = 0u;
                    *(uint32_t*)(r1t + SWZ(off + 4)) = 0u;
                }
            }
        }
        if (tid < 64) Bws[tid] = BW[(size_t)bz * QL + jc0 + tid];
        if (tid < 95) Brs[tid] = BR[(size_t)bz * PL + gb + tid];
        __syncthreads();

        // ---- HMMA: ac (32x64, warp 16x16) and bd' (32x96, warp 16x24) ----
        float aac[2][4], abd[3][4];
#pragma unroll
        for (int ni = 0; ni < 2; ++ni)
#pragma unroll
            for (int q = 0; q < 4; ++q) aac[ni][q] = 0.f;
#pragma unroll
        for (int ni = 0; ni < 3; ++ni)
#pragma unroll
            for (int q = 0; q < 4; ++q) abd[ni][q] = 0.f;

        const int asel[3] = {0, 0, 1};
        const int bsel[3] = {0, 1, 0};
#pragma unroll
        for (int t = 0; t < 3; ++t) {
            const uint32_t At = su + SA_Q0 + asel[t] * 4096;
            const uint32_t Kt = su + SA_K0 + bsel[t] * 8192;
            const uint32_t Rt = su + SA_R0 + bsel[t] * 12288;
#pragma unroll
            for (int ks = 0; ks < 4; ++ks) {
                uint32_t af[4], bk[2][2], br_[3][2];
                {
                    const int row = wy * 16 + a_row;
                    ldsm_x4(af, At + SWZ(row * 128 + ks * 32 + a_kb));
                }
#pragma unroll
                for (int ni = 0; ni < 2; ++ni) {
                    const int row = wx * 16 + ni * 8 + b_row;
                    ldsm_x2(bk[ni], Kt + SWZ(row * 128 + ks * 32 + b_kb));
                }
#pragma unroll
                for (int ni = 0; ni < 3; ++ni) {
                    const int row = wx * 24 + ni * 8 + b_row;
                    ldsm_x2(br_[ni], Rt + SWZ(row * 128 + ks * 32 + b_kb));
                }
#pragma unroll
                for (int ni = 0; ni < 2; ++ni) mma_bf16(aac[ni], af, bk[ni]);
#pragma unroll
                for (int ni = 0; ni < 3; ++ni) mma_bf16(abd[ni], af, br_[ni]);
            }
        }
        // write frags to smem
        const int er = lane >> 2, ec = (lane & 3) * 2;
        {
            const int r0 = wy * 16 + er;
#pragma unroll
            for (int ni = 0; ni < 2; ++ni) {
                const int c = wx * 16 + ni * 8 + ec;
                *(float2*)&Sc[r0 * 68 + c]       = make_float2(aac[ni][0], aac[ni][1]);
                *(float2*)&Sc[(r0 + 8) * 68 + c] = make_float2(aac[ni][2], aac[ni][3]);
            }
#pragma unroll
            for (int ni = 0; ni < 3; ++ni) {
                const int c = wx * 24 + ni * 8 + ec;
                *(float2*)&Sb[r0 * 100 + c]       = make_float2(abd[ni][0], abd[ni][1]);
                *(float2*)&Sb[(r0 + 8) * 100 + c] = make_float2(abd[ni][2], abd[ni][3]);
            }
        }
        __syncthreads();

        // ---- assemble full scores into Sc ----
#pragma unroll
        for (int m = 0; m < 2; ++m) {
            const int il = ty * 2 + m;
            const int i = i0 + il;
#pragma unroll
            for (int q = 0; q < 4; ++q) {
                const int jl = tx * 4 + q;
                const int j = jc0 + jl;
                const int t = jl - il + 31;
                const size_t ij = (size_t)(i * QL + j) * BSZ + b;
                const float2 sg = *(const float2*)&seg[ij * 2];
                const float mk = mask[ij];
                float s = Sc[il * 68 + jl] + Sb[il * 100 + t] + Bws[jl] + Brs[t]
                        + sg.x * efx[m] + sg.y * efy[m];
                Sc[il * 68 + jl] = s * SCALEF - BIGF * mk;
            }
        }
        __syncthreads();

        // ---- online softmax: warp w covers rows w*4..w*4+3, 8 lanes/row ----
        {
            const int r = wid * 4 + (lane >> 3);
            const int c8 = lane & 7;
            float cmax = -BIGF;
#pragma unroll
            for (int u = 0; u < 8; ++u)
                cmax = fmaxf(cmax, Sc[r * 68 + c8 * 8 + u]);
            cmax = fmaxf(cmax, __shfl_xor_sync(0xffffffffu, cmax, 1));
            cmax = fmaxf(cmax, __shfl_xor_sync(0xffffffffu, cmax, 2));
            cmax = fmaxf(cmax, __shfl_xor_sync(0xffffffffu, cmax, 4));
            const float m_old = rowm[r];
            const float m_new = fmaxf(m_old, cmax);
            float psum = 0.f;
#pragma unroll
            for (int u = 0; u < 8; ++u) {
                const int idx = r * 68 + c8 * 8 + u;
                const float p = __expf(Sc[idx] - m_new);
                Sc[idx] = p;
                psum += p;
            }
            psum += __shfl_xor_sync(0xffffffffu, psum, 1);
            psum += __shfl_xor_sync(0xffffffffu, psum, 2);
            psum += __shfl_xor_sync(0xffffffffu, psum, 4);
            if (c8 == 0) {
                const float f = __expf(m_old - m_new);
                rowm[r] = m_new;
                rows[r] = rows[r] * f + psum;
                rowf[r] = f;
            }
        }
        __syncthreads();

        // ---- AV accumulate (SIMT fp32) ----
        {
#pragma unroll
            for (int m = 0; m < 2; ++m) {
                const float fr = rowf[ty * 2 + m];
#pragma unroll
                for (int q = 0; q < 4; ++q) O[m][q] *= fr;
            }
#pragma unroll 4
            for (int jl = 0; jl < 64; ++jl) {
                float p[2], vv[4];
#pragma unroll
                for (int m = 0; m < 2; ++m) p[m] = Sc[(ty * 2 + m) * 68 + jl];
#pragma unroll
                for (int q = 0; q < 4; ++q) vv[q] = Vc[jl * 68 + tx * 4 + q];
#pragma unroll
                for (int m = 0; m < 2; ++m)
#pragma unroll
                    for (int q = 0; q < 4; ++q)
                        O[m][q] += p[m] * vv[q];
            }
        }
    }

    // ---- finalize: normalize + direct bf16 split to AOs0/AOs1 ----
    __syncthreads();
#pragma unroll
    for (int m = 0; m < 2; ++m) {
        const int il = ty * 2 + m;
        const float inv = 1.f / rows[il];
        __nv_bfloat16 a[4], c[4];
#pragma unroll
        for (int q = 0; q < 4; ++q) split2f(O[m][q] * inv, a[q], c[q]);
        const size_t o = ((size_t)((i0 + il) * BSZ + b)) * HID + n * 64 + tx * 4;
        *(uint32_t*)&AOs0[o]     = bpack(a[0], a[1]);
        *(uint32_t*)&AOs0[o + 2] = bpack(a[2], a[3]);
        *(uint32_t*)&AOs1[o]     = bpack(c[0], c[1]);
        *(uint32_t*)&AOs1[o + 2] = bpack(c[2], c[3]);
    }
}

// ============================ LayerNorm ============================
__global__ void ln_kernel(const float* __restrict__ PR, const float* __restrict__ HS,
                          const float* __restrict__ gamma, const float* __restrict__ beta,
                          float* __restrict__ out)
{
    __shared__ float sred[2][8];
    const int row = blockIdx.x;
    const int tid = threadIdx.x;
    const float* pr = PR + (size_t)row * HID;
    const float* hs = HS + (size_t)row * HID;
    float x[4], s = 0.f, s2 = 0.f;
#pragma unroll
    for (int t = 0; t < 4; ++t) {
        int c = tid + 256 * t;
        float v = pr[c] + hs[c];
        x[t] = v; s += v; s2 += v * v;
    }
#pragma unroll
    for (int o = 16; o; o >>= 1) {
        s  += __shfl_xor_sync(0xffffffffu, s,  o);
        s2 += __shfl_xor_sync(0xffffffffu, s2, o);
    }
    if ((tid & 31) == 0) { sred[0][tid >> 5] = s; sred[1][tid >> 5] = s2; }
    __syncthreads();
    if (tid < 32) {
        float a = (tid < 8) ? sred[0][tid] : 0.f;
        float b2 = (tid < 8) ? sred[1][tid] : 0.f;
#pragma unroll
        for (int o = 4; o; o >>= 1) {
            a  += __shfl_xor_sync(0xffffffffu, a,  o);
            b2 += __shfl_xor_sync(0xffffffffu, b2, o);
        }
        if (tid == 0) { sred[0][0] = a; sred[1][0] = b2; }
    }
    __syncthreads();
    const float mean = sred[0][0] * (1.f / 1024.f);
    const float var  = sred[1][0] * (1.f / 1024.f) - mean * mean;
    const float inv  = rsqrtf(var + 1e-5f);
#pragma unroll
    for (int t = 0; t < 4; ++t) {
        int c = tid + 256 * t;
        out[(size_t)row * HID + c] = (x[t] - mean) * inv * gamma[c] + beta[c];
    }
}

// ============================ launch ============================
extern "C" void kernel_launch(void* const* d_in, const int* in_sizes, int n_in,
                              void* d_out, int out_size)
{
    (void)in_sizes; (void)n_in; (void)out_size;
    const float* hs    = (const float*)d_in[0];
    const float* pos   = (const float*)d_in[1];
    const float* seg   = (const float*)d_in[2];
    const float* mask  = (const float*)d_in[3];
    const float* wq    = (const float*)d_in[4];
    const float* wk    = (const float*)d_in[5];
    const float* wv    = (const float*)d_in[6];
    const float* wr    = (const float*)d_in[7];
    const float* wo    = (const float*)d_in[8];
    const float* rwb   = (const float*)d_in[9];
    const float* rrb   = (const float*)d_in[10];
    const float* rsb   = (const float*)d_in[11];
    const float* segm  = (const float*)d_in[12];
    const float* gamma = (const float*)d_in[13];
    const float* beta  = (const float*)d_in[14];
    float* out = (float*)d_out;

    float *QKVd, *KRd, *PRd, *EF1d, *BWd, *BRd;
    cudaGetSymbolAddress((void**)&QKVd, g_QKV);
    cudaGetSymbolAddress((void**)&KRd, g_KR);
    cudaGetSymbolAddress((void**)&PRd, g_PR);
    cudaGetSymbolAddress((void**)&EF1d, g_EF1);
    cudaGetSymbolAddress((void**)&BWd, g_BW);
    cudaGetSymbolAddress((void**)&BRd, g_BR);

    __nv_bfloat16 *HA0, *HA1, *PA0, *PA1, *AOs0, *AOs1, *WB0, *WB1;
    cudaGetSymbolAddress((void**)&HA0, g_HA0);
    cudaGetSymbolAddress((void**)&HA1, g_HA1);
    cudaGetSymbolAddress((void**)&PA0, g_PA0);
    cudaGetSymbolAddress((void**)&PA1, g_PA1);
    cudaGetSymbolAddress((void**)&AOs0, g_AOs0);
    cudaGetSymbolAddress((void**)&AOs1, g_AOs1);
    cudaGetSymbolAddress((void**)&WB0, g_WB0);
    cudaGetSymbolAddress((void**)&WB1, g_WB1);

    cudaFuncSetAttribute(gemm_mma, cudaFuncAttributeMaxDynamicSharedMemorySize, GEMM_SMEM);
    cudaFuncSetAttribute(attn_kernel, cudaFuncAttributeMaxDynamicSharedMemorySize, ATTN_SMEM);

    const size_t WSZ = (size_t)HID * HID;

    // Splits
    split2_kernel<<<(IB*HID/4 + 255)/256, 256>>>(hs,  HA0, HA1, IB*HID/4);
    split2_kernel<<<(JBR*HID/4 + 255)/256, 256>>>(pos, PA0, PA1, JBR*HID/4);
    dim3 gt(32, 32), bt(32, 8);
    tsplit2_kernel<<<gt, bt>>>(wq, WB0 + 0*WSZ, WB1 + 0*WSZ);
    tsplit2_kernel<<<gt, bt>>>(wk, WB0 + 1*WSZ, WB1 + 1*WSZ);
    tsplit2_kernel<<<gt, bt>>>(wv, WB0 + 2*WSZ, WB1 + 2*WSZ);
    tsplit2_kernel<<<gt, bt>>>(wr, WB0 + 3*WSZ, WB1 + 3*WSZ);
    split2_kernel<<<(HID*HID/4 + 255)/256, 256>>>(wo, WB0 + 4*WSZ, WB1 + 4*WSZ, HID*HID/4);

    // Fused QKV projection (N = 3072) + KR projection
    dim3 gqkv(QKVW / 128, IB / 128);   // (24, 32)
    gemm_mma<<<gqkv, 256, GEMM_SMEM>>>(HA0, HA1, WB0, WB1, QKVd, IB, QKVW, HID);
    dim3 gr(8, 64);
    gemm_mma<<<gr, 256, GEMM_SMEM>>>(PA0, PA1, WB0+3*WSZ, WB1+3*WSZ, KRd, JBR, HID, HID);

    // Bias precomputes
    ef1_kernel    <<<IB * NH / 4, 128>>>(QKVd, rsb, segm, EF1d);
    rowbias_kernel<<<QL * BSZ * NH / 4, 128>>>(QKVd, QKVW, 1024, rwb, BWd, QL);
    rowbias_kernel<<<PL * BSZ * NH / 4, 128>>>(KRd,  HID,  0,    rrb, BRd, PL);

    // Fused flash attention (writes bf16 AO splits directly)
    dim3 ga(QL / 32, BNH);             // (16, 128)
    attn_kernel<<<ga, 256, ATTN_SMEM>>>(QKVd, KRd, EF1d, BWd, BRd, seg, mask, AOs0, AOs1);

    // Output projection (HMMA) + LN
    dim3 go(8, 32);
    gemm_mma<<<go, 256, GEMM_SMEM>>>(AOs0, AOs1, WB0+4*WSZ, WB1+4*WSZ, PRd, IB, HID, HID);
    ln_kernel<<<IB, 256>>>(PRd, hs, gamma, beta, out);
}

// round 14
// speedup vs baseline: 1.1157x; 1.1157x over previous
#include <cuda_runtime.h>
#include <cuda_bf16.h>
#include <math.h>
#include <stdint.h>

#define QL   512
#define BSZ  8
#define HID  1024
#define NH   16
#define HD   64
#define PL   1024
#define IB   (QL*BSZ)
#define JBR  (PL*BSZ)
#define BNH  (BSZ*NH)
#define QKVW 3072
#define SCALEF 0.125f
#define BIGF   1e30f

// -------- fp32 scratch --------
__device__ float g_QKV[IB*QKVW];    // fused Q|K|V projections [4096][3072]
__device__ float g_KR[JBR*HID];
__device__ float g_PR[IB*HID];
__device__ float g_EF1[IB*NH*2];
__device__ float g_BW[BNH*QL];
__device__ float g_BR[BNH*PL];

// -------- bf16 split scratch --------
__device__ __nv_bfloat16 g_HA0[IB*HID],  g_HA1[IB*HID];
__device__ __nv_bfloat16 g_PA0[JBR*HID], g_PA1[JBR*HID];
__device__ __nv_bfloat16 g_AOs0[IB*HID], g_AOs1[IB*HID];
__device__ __nv_bfloat16 g_WB0[5*HID*HID], g_WB1[5*HID*HID];
// pre-split activations for the attention kernel
__device__ __nv_bfloat16 g_QKVs0[IB*QKVW], g_QKVs1[IB*QKVW];
__device__ __nv_bfloat16 g_KRs0[JBR*HID],  g_KRs1[JBR*HID];

// ============================ helpers ============================
__device__ __forceinline__ uint32_t smem_u32(const void* p) {
    uint32_t a;
    asm("{ .reg .u64 t; cvta.to.shared.u64 t, %1; cvt.u32.u64 %0, t; }"
        : "=r"(a) : "l"(p));
    return a;
}
#define SWZ(off) ((off) ^ (((off) >> 3) & 0x70))

__device__ __forceinline__ void ldsm_x4(uint32_t* r, uint32_t addr) {
    asm volatile("ldmatrix.sync.aligned.m8n8.x4.shared.b16 {%0,%1,%2,%3}, [%4];"
        : "=r"(r[0]), "=r"(r[1]), "=r"(r[2]), "=r"(r[3]) : "r"(addr));
}
__device__ __forceinline__ void ldsm_x2(uint32_t* r, uint32_t addr) {
    asm volatile("ldmatrix.sync.aligned.m8n8.x2.shared.b16 {%0,%1}, [%2];"
        : "=r"(r[0]), "=r"(r[1]) : "r"(addr));
}
__device__ __forceinline__ void mma_bf16(float* d, const uint32_t* a, const uint32_t* b) {
    asm volatile("mma.sync.aligned.m16n8k16.row.col.f32.bf16.bf16.f32 "
        "{%0,%1,%2,%3}, {%4,%5,%6,%7}, {%8,%9}, {%0,%1,%2,%3};"
        : "+f"(d[0]), "+f"(d[1]), "+f"(d[2]), "+f"(d[3])
        : "r"(a[0]), "r"(a[1]), "r"(a[2]), "r"(a[3]), "r"(b[0]), "r"(b[1]));
}
__device__ __forceinline__ void split2f(float v, __nv_bfloat16& a0, __nv_bfloat16& a1) {
    a0 = __float2bfloat16_rn(v);
    a1 = __float2bfloat16_rn(v - __bfloat162float(a0));
}
__device__ __forceinline__ uint32_t bpack(__nv_bfloat16 lo, __nv_bfloat16 hi) {
    __nv_bfloat162 t = __halves2bfloat162(lo, hi);
    return *(uint32_t*)&t;
}

// ============================ split kernels ============================
__global__ void split2_kernel(const float* __restrict__ X,
    __nv_bfloat16* __restrict__ S0, __nv_bfloat16* __restrict__ S1, int n4)
{
    int i = blockIdx.x * blockDim.x + threadIdx.x;
    if (i >= n4) return;
    float4 v = ((const float4*)X)[i];
    __nv_bfloat16 a[4], b[4];
    split2f(v.x, a[0], b[0]);
    split2f(v.y, a[1], b[1]);
    split2f(v.z, a[2], b[2]);
    split2f(v.w, a[3], b[3]);
    uint32_t* p0 = (uint32_t*)S0;
    uint32_t* p1 = (uint32_t*)S1;
    p0[2*i]   = bpack(a[0], a[1]);
    p0[2*i+1] = bpack(a[2], a[3]);
    p1[2*i]   = bpack(b[0], b[1]);
    p1[2*i+1] = bpack(b[2], b[3]);
}

__global__ void tsplit2_kernel(const float* __restrict__ W,
    __nv_bfloat16* __restrict__ T0, __nv_bfloat16* __restrict__ T1)
{
    __shared__ float t[32][33];
    const int n0 = blockIdx.x * 32, k0 = blockIdx.y * 32;
    const int tx = threadIdx.x, ty = threadIdx.y;
    for (int r = ty; r < 32; r += 8)
        t[r][tx] = W[(size_t)(k0 + r) * HID + n0 + tx];
    __syncthreads();
    for (int r = ty; r < 32; r += 8) {
        float v = t[tx][r];
        __nv_bfloat16 a, b; split2f(v, a, b);
        size_t o = (size_t)(n0 + r) * HID + k0 + tx;
        T0[o] = a; T1[o] = b;
    }
}

// ============================ HMMA GEMM (known-good) ============================
#define GEMM_SMEM 65536

__global__ __launch_bounds__(256, 2) void gemm_mma(
    const __nv_bfloat16* __restrict__ A0, const __nv_bfloat16* __restrict__ A1,
    const __nv_bfloat16* __restrict__ B0, const __nv_bfloat16* __restrict__ B1,
    float* __restrict__ C, int M, int N, int K)
{
    extern __shared__ char sm[];
    const uint32_t su = smem_u32(sm);
    const int tid = threadIdx.x, lane = tid & 31, wid = tid >> 5;
    const int wm = (wid >> 2) * 64, wn = (wid & 3) * 32;
    const int m0 = blockIdx.y * 128, n0 = blockIdx.x * 128;

    float acc[4][4][4];
#pragma unroll
    for (int mi = 0; mi < 4; ++mi)
#pragma unroll
        for (int ni = 0; ni < 4; ++ni)
#pragma unroll
            for (int q = 0; q < 4; ++q) acc[mi][ni][q] = 0.f;

    const __nv_bfloat16* Ap[2] = {A0, A1};
    const __nv_bfloat16* Bp[2] = {B0, B1};
    const int a_row = lane & 15, a_kb = (lane >> 4) * 16;
    const int b_row = lane & 7,  b_kb = ((lane >> 3) & 1) * 16;

    for (int k0 = 0; k0 < K; k0 += 64) {
        __syncthreads();
#pragma unroll
        for (int s = 0; s < 2; ++s) {
            const char* ag = (const char*)(Ap[s] + (size_t)m0 * K + k0);
            const char* bg = (const char*)(Bp[s] + (size_t)n0 * K + k0);
            char* at = sm + s * 16384;
            char* bt = sm + 32768 + s * 16384;
#pragma unroll
            for (int i = 0; i < 4; ++i) {
                const int off = (tid + i * 256) * 16;
                const int row = off >> 7, cb = off & 127;
                const size_t g = (size_t)row * K * 2 + cb;
                *(uint4*)(at + SWZ(off)) = *(const uint4*)(ag + g);
                *(uint4*)(bt + SWZ(off)) = *(const uint4*)(bg + g);
            }
        }
        __syncthreads();

        const int asel[3] = {0, 0, 1};
        const int bsel[3] = {0, 1, 0};
#pragma unroll
        for (int t = 0; t < 3; ++t) {
            const uint32_t At = su + asel[t] * 16384;
            const uint32_t Bt = su + 32768 + bsel[t] * 16384;
#pragma unroll
            for (int ks = 0; ks < 4; ++ks) {
                uint32_t af[4][4], bf[4][2];
#pragma unroll
                for (int mi = 0; mi < 4; ++mi) {
                    const int row = wm + mi * 16 + a_row;
                    const int off = row * 128 + ks * 32 + a_kb;
                    ldsm_x4(af[mi], At + SWZ(off));
                }
#pragma unroll
                for (int ni = 0; ni < 4; ++ni) {
                    const int row = wn + ni * 8 + b_row;
                    const int off = row * 128 + ks * 32 + b_kb;
                    ldsm_x2(bf[ni], Bt + SWZ(off));
                }
#pragma unroll
                for (int mi = 0; mi < 4; ++mi)
#pragma unroll
                    for (int ni = 0; ni < 4; ++ni)
                        mma_bf16(acc[mi][ni], af[mi], bf[ni]);
            }
        }
    }

    const int er = lane >> 2, ec = (lane & 3) * 2;
#pragma unroll
    for (int mi = 0; mi < 4; ++mi) {
#pragma unroll
        for (int ni = 0; ni < 4; ++ni) {
            const int row = m0 + wm + mi * 16 + er;
            const int col = n0 + wn + ni * 8 + ec;
            float2 v0 = {acc[mi][ni][0], acc[mi][ni][1]};
            float2 v1 = {acc[mi][ni][2], acc[mi][ni][3]};
            *(float2*)(C + (size_t)row * N + col)       = v0;
            *(float2*)(C + (size_t)(row + 8) * N + col) = v1;
        }
    }
}

// ============================ small precompute kernels ============================
__global__ void ef1_kernel(const float* __restrict__ QKV, const float* __restrict__ rsb,
                           const float* __restrict__ segm, float* __restrict__ EF1)
{
    int w = (blockIdx.x * blockDim.x + threadIdx.x) >> 5;
    int lane = threadIdx.x & 31;
    int n = w & 15, ib = w >> 4;
    const float* qp = QKV + (size_t)ib * QKVW + n * 64;
    const float* bp = rsb + n * 64;
    float q0 = qp[lane] + bp[lane];
    float q1 = qp[lane + 32] + bp[lane + 32];
    float s0 = q0 * segm[n*64 + lane]        + q1 * segm[n*64 + lane + 32];
    float s1 = q0 * segm[1024 + n*64 + lane] + q1 * segm[1024 + n*64 + lane + 32];
#pragma unroll
    for (int o = 16; o; o >>= 1) {
        s0 += __shfl_xor_sync(0xffffffffu, s0, o);
        s1 += __shfl_xor_sync(0xffffffffu, s1, o);
    }
    if (lane == 0) { EF1[w*2] = s0; EF1[w*2 + 1] = s1; }
}

__global__ void rowbias_kernel(const float* __restrict__ X, int stride, int coloff,
                               const float* __restrict__ bias,
                               float* __restrict__ OUT, int JLEN)
{
    int w = (blockIdx.x * blockDim.x + threadIdx.x) >> 5;
    int lane = threadIdx.x & 31;
    int n = w & 15, rem = w >> 4;
    int b = rem & 7, j = rem >> 3;
    const float* xp = X + (size_t)(j * BSZ + b) * stride + coloff + n * 64;
    float v = xp[lane] * bias[n*64 + lane] + xp[lane + 32] * bias[n*64 + lane + 32];
#pragma unroll
    for (int o = 16; o; o >>= 1) v += __shfl_xor_sync(0xffffffffu, v, o);
    if (lane == 0) OUT[(size_t)(b * 16 + n) * JLEN + j] = v;
}

// ============================ fused flash attention (i-tile 64, presplit bf16) ============================
// One CTA per (i-tile of 64, b, n). 8 j-chunks of 64. Band = 127 rows (+1 pad).
// Loads are pure uint4 copies from pre-split bf16 buffers (no in-loop convert).
#define SA_Q0   0        // 64x64 bf16 = 8KB per split
#define SA_Q1   8192
#define SA_K0   16384    // 64x64 bf16
#define SA_K1   24576
#define SA_R0   32768    // 128x64 bf16 = 16KB per split (row 127 = pad)
#define SA_R1   49152
#define SA_SB   65536    // bd' fp32 [64][132]
#define SA_SC   99328    // score/P fp32 [64][68]
#define SA_VC   116736   // V chunk fp32 [64][68]
#define SA_RM   134144   // rowm [64]
#define SA_RS   134400   // rows [64]
#define SA_RF   134656   // rowf [64]
#define SA_BW   134912   // Bw [64]
#define SA_BR   135168   // Br [127] (+pad)
#define ATTN_SMEM 135680

__global__ __launch_bounds__(256, 1) void attn_kernel(
    const float* __restrict__ QKV,
    const __nv_bfloat16* __restrict__ QKVs0, const __nv_bfloat16* __restrict__ QKVs1,
    const __nv_bfloat16* __restrict__ KRs0,  const __nv_bfloat16* __restrict__ KRs1,
    const float* __restrict__ EF1, const float* __restrict__ BW,
    const float* __restrict__ BR, const float* __restrict__ seg,
    const float* __restrict__ mask,
    __nv_bfloat16* __restrict__ AOs0, __nv_bfloat16* __restrict__ AOs1)
{
    extern __shared__ char sm[];
    const uint32_t su = smem_u32(sm);
    float* Sb = (float*)(sm + SA_SB);
    float* Sc = (float*)(sm + SA_SC);
    float* Vc = (float*)(sm + SA_VC);
    float* rowm = (float*)(sm + SA_RM);
    float* rows = (float*)(sm + SA_RS);
    float* rowf = (float*)(sm + SA_RF);
    float* Bws  = (float*)(sm + SA_BW);
    float* Brs  = (float*)(sm + SA_BR);

    const int tid = threadIdx.x, lane = tid & 31, wid = tid >> 5;
    const int i0 = blockIdx.x * 64;
    const int bz = blockIdx.y;            // b*16+n
    const int b = bz >> 4, n = bz & 15;
    const int wy = wid >> 2, wx = wid & 3;
    const int ty = tid >> 4, tx = tid & 15;

    // ---- load Q tile: pure bf16 copies (2 x 16B per thread per split) ----
    {
#pragma unroll
        for (int k = 0; k < 2; ++k) {
            const int off = (tid + k * 256) * 16;      // < 8192
            const int row = off >> 7, cb = off & 127;
            const size_t g = ((size_t)((i0 + row) * BSZ + b) * QKVW + n * 64) * 2 + cb;
            *(uint4*)(sm + SA_Q0 + SWZ(off)) = *(const uint4*)((const char*)QKVs0 + g);
            *(uint4*)(sm + SA_Q1 + SWZ(off)) = *(const uint4*)((const char*)QKVs1 + g);
        }
    }
    if (tid < 64) { rowm[tid] = -BIGF; rows[tid] = 0.f; }

    float efx[4], efy[4];
#pragma unroll
    for (int m = 0; m < 4; ++m) {
        const int i = i0 + ty * 4 + m;
        const float2 ef = *(const float2*)&EF1[((size_t)(i * BSZ + b) * 16 + n) * 2];
        efx[m] = ef.x; efy[m] = ef.y;
    }

    float O[4][4];
#pragma unroll
    for (int m = 0; m < 4; ++m)
#pragma unroll
        for (int q = 0; q < 4; ++q) O[m][q] = 0.f;

    const int a_row = lane & 15, a_kb = (lane >> 4) * 16;
    const int b_row = lane & 7,  b_kb = ((lane >> 3) & 1) * 16;

    for (int jc0 = 0; jc0 < QL; jc0 += 64) {
        const int gb = jc0 - i0 + 449;    // first KR band row (global), in [1, 897]
        __syncthreads();   // previous chunk fully consumed

        // ---- K chunk: bf16 copies ----
#pragma unroll
        for (int k = 0; k < 2; ++k) {
            const int off = (tid + k * 256) * 16;      // < 8192
            const int row = off >> 7, cb = off & 127;
            const size_t g = ((size_t)((jc0 + row) * BSZ + b) * QKVW + 1024 + n * 64) * 2 + cb;
            *(uint4*)(sm + SA_K0 + SWZ(off)) = *(const uint4*)((const char*)QKVs0 + g);
            *(uint4*)(sm + SA_K1 + SWZ(off)) = *(const uint4*)((const char*)QKVs1 + g);
        }
        // ---- V chunk: fp32 ----
        {
            const int jl = tid >> 2, d0 = (tid & 3) * 16;
            const float* vp = QKV + (size_t)((jc0 + jl) * BSZ + b) * QKVW + 2048 + n * 64 + d0;
#pragma unroll
            for (int u = 0; u < 4; ++u)
                *(float4*)&Vc[jl * 68 + d0 + u * 4] = *(const float4*)(vp + u * 4);
        }
        // ---- KR band 127 rows: bf16 copies (row 127 pad zero) ----
#pragma unroll
        for (int k = 0; k < 4; ++k) {
            const int off = (tid + k * 256) * 16;      // < 16384
            const int row = off >> 7, cb = off & 127;
            if (row < 127) {
                const size_t g = ((size_t)((gb + row) * BSZ + b) * HID + n * 64) * 2 + cb;
                *(uint4*)(sm + SA_R0 + SWZ(off)) = *(const uint4*)((const char*)KRs0 + g);
                *(uint4*)(sm + SA_R1 + SWZ(off)) = *(const uint4*)((const char*)KRs1 + g);
            } else {
                uint4 z = {0u, 0u, 0u, 0u};
                *(uint4*)(sm + SA_R0 + SWZ(off)) = z;
                *(uint4*)(sm + SA_R1 + SWZ(off)) = z;
            }
        }
        if (tid < 64)  Bws[tid] = BW[(size_t)bz * QL + jc0 + tid];
        if (tid < 127) Brs[tid] = BR[(size_t)bz * PL + gb + tid];
        __syncthreads();

        // ---- HMMA: ac (64x64) and bd' (64x128) ----
        float aac[2][2][4], abd[2][4][4];
#pragma unroll
        for (int mi = 0; mi < 2; ++mi) {
#pragma unroll
            for (int ni = 0; ni < 2; ++ni)
#pragma unroll
                for (int q = 0; q < 4; ++q) aac[mi][ni][q] = 0.f;
#pragma unroll
            for (int ni = 0; ni < 4; ++ni)
#pragma unroll
                for (int q = 0; q < 4; ++q) abd[mi][ni][q] = 0.f;
        }
        const int asel[3] = {0, 0, 1};
        const int bsel[3] = {0, 1, 0};
#pragma unroll
        for (int t = 0; t < 3; ++t) {
            const uint32_t At = su + SA_Q0 + asel[t] * 8192;
            const uint32_t Kt = su + SA_K0 + bsel[t] * 8192;
            const uint32_t Rt = su + SA_R0 + bsel[t] * 16384;
#pragma unroll
            for (int ks = 0; ks < 4; ++ks) {
                uint32_t af[2][4], bk[2][2], br_[4][2];
#pragma unroll
                for (int mi = 0; mi < 2; ++mi) {
                    const int row = wy * 32 + mi * 16 + a_row;
                    ldsm_x4(af[mi], At + SWZ(row * 128 + ks * 32 + a_kb));
                }
#pragma unroll
                for (int ni = 0; ni < 2; ++ni) {
                    const int row = wx * 16 + ni * 8 + b_row;
                    ldsm_x2(bk[ni], Kt + SWZ(row * 128 + ks * 32 + b_kb));
                }
#pragma unroll
                for (int ni = 0; ni < 4; ++ni) {
                    const int row = wx * 32 + ni * 8 + b_row;
                    ldsm_x2(br_[ni], Rt + SWZ(row * 128 + ks * 32 + b_kb));
                }
#pragma unroll
                for (int mi = 0; mi < 2; ++mi) {
#pragma unroll
                    for (int ni = 0; ni < 2; ++ni) mma_bf16(aac[mi][ni], af[mi], bk[ni]);
#pragma unroll
                    for (int ni = 0; ni < 4; ++ni) mma_bf16(abd[mi][ni], af[mi], br_[ni]);
                }
            }
        }
        // write frags to smem
        const int er = lane >> 2, ec = (lane & 3) * 2;
#pragma unroll
        for (int mi = 0; mi < 2; ++mi) {
            const int r0 = wy * 32 + mi * 16 + er;
#pragma unroll
            for (int ni = 0; ni < 2; ++ni) {
                const int c = wx * 16 + ni * 8 + ec;
                *(float2*)&Sc[r0 * 68 + c]       = make_float2(aac[mi][ni][0], aac[mi][ni][1]);
                *(float2*)&Sc[(r0 + 8) * 68 + c] = make_float2(aac[mi][ni][2], aac[mi][ni][3]);
            }
#pragma unroll
            for (int ni = 0; ni < 4; ++ni) {
                const int c = wx * 32 + ni * 8 + ec;
                *(float2*)&Sb[r0 * 132 + c]       = make_float2(abd[mi][ni][0], abd[mi][ni][1]);
                *(float2*)&Sb[(r0 + 8) * 132 + c] = make_float2(abd[mi][ni][2], abd[mi][ni][3]);
            }
        }
        __syncthreads();

        // ---- assemble full scores into Sc ----
#pragma unroll
        for (int m = 0; m < 4; ++m) {
            const int il = ty * 4 + m;
            const int i = i0 + il;
#pragma unroll
            for (int q = 0; q < 4; ++q) {
                const int jl = tx * 4 + q;
                const int j = jc0 + jl;
                const int t = jl - il + 63;
                const size_t ij = (size_t)(i * QL + j) * BSZ + b;
                const float2 sg = *(const float2*)&seg[ij * 2];
                const float mk = mask[ij];
                float s = Sc[il * 68 + jl] + Sb[il * 132 + t] + Bws[jl] + Brs[t]
                        + sg.x * efx[m] + sg.y * efy[m];
                Sc[il * 68 + jl] = s * SCALEF - BIGF * mk;
            }
        }
        __syncthreads();

        // ---- online softmax row stats (warp w: rows w*8 + lane/4) ----
        {
            const int r = wid * 8 + (lane >> 2);
            const int c4 = lane & 3;
            float cmax = -BIGF;
#pragma unroll
            for (int u = 0; u < 16; ++u)
                cmax = fmaxf(cmax, Sc[r * 68 + c4 * 16 + u]);
            cmax = fmaxf(cmax, __shfl_xor_sync(0xffffffffu, cmax, 1));
            cmax = fmaxf(cmax, __shfl_xor_sync(0xffffffffu, cmax, 2));
            const float m_old = rowm[r];
            const float m_new = fmaxf(m_old, cmax);
            float psum = 0.f;
#pragma unroll
            for (int u = 0; u < 16; ++u) {
                const int idx = r * 68 + c4 * 16 + u;
                const float p = __expf(Sc[idx] - m_new);
                Sc[idx] = p;
                psum += p;
            }
            psum += __shfl_xor_sync(0xffffffffu, psum, 1);
            psum += __shfl_xor_sync(0xffffffffu, psum, 2);
            if (c4 == 0) {
                const float f = __expf(m_old - m_new);
                rowm[r] = m_new;
                rows[r] = rows[r] * f + psum;
                rowf[r] = f;
            }
        }
        __syncthreads();

        // ---- AV accumulate (SIMT fp32) ----
        {
            float fr[4];
#pragma unroll
            for (int m = 0; m < 4; ++m) {
                fr[m] = rowf[ty * 4 + m];
#pragma unroll
                for (int q = 0; q < 4; ++q) O[m][q] *= fr[m];
            }
#pragma unroll 4
            for (int jl = 0; jl < 64; ++jl) {
                float p[4], vv[4];
#pragma unroll
                for (int m = 0; m < 4; ++m) p[m] = Sc[(ty * 4 + m) * 68 + jl];
#pragma unroll
                for (int q = 0; q < 4; ++q) vv[q] = Vc[jl * 68 + tx * 4 + q];
#pragma unroll
                for (int m = 0; m < 4; ++m)
#pragma unroll
                    for (int q = 0; q < 4; ++q)
                        O[m][q] += p[m] * vv[q];
            }
        }
    }

    // ---- finalize: normalize + direct bf16 split to AOs0/AOs1 ----
    __syncthreads();
#pragma unroll
    for (int m = 0; m < 4; ++m) {
        const int il = ty * 4 + m;
        const float inv = 1.f / rows[il];
        __nv_bfloat16 a[4], c[4];
#pragma unroll
        for (int q = 0; q < 4; ++q) split2f(O[m][q] * inv, a[q], c[q]);
        const size_t o = ((size_t)((i0 + il) * BSZ + b)) * HID + n * 64 + tx * 4;
        *(uint32_t*)&AOs0[o]     = bpack(a[0], a[1]);
        *(uint32_t*)&AOs0[o + 2] = bpack(a[2], a[3]);
        *(uint32_t*)&AOs1[o]     = bpack(c[0], c[1]);
        *(uint32_t*)&AOs1[o + 2] = bpack(c[2], c[3]);
    }
}

// ============================ LayerNorm ============================
__global__ void ln_kernel(const float* __restrict__ PR, const float* __restrict__ HS,
                          const float* __restrict__ gamma, const float* __restrict__ beta,
                          float* __restrict__ out)
{
    __shared__ float sred[2][8];
    const int row = blockIdx.x;
    const int tid = threadIdx.x;
    const float* pr = PR + (size_t)row * HID;
    const float* hs = HS + (size_t)row * HID;
    float x[4], s = 0.f, s2 = 0.f;
#pragma unroll
    for (int t = 0; t < 4; ++t) {
        int c = tid + 256 * t;
        float v = pr[c] + hs[c];
        x[t] = v; s += v; s2 += v * v;
    }
#pragma unroll
    for (int o = 16; o; o >>= 1) {
        s  += __shfl_xor_sync(0xffffffffu, s,  o);
        s2 += __shfl_xor_sync(0xffffffffu, s2, o);
    }
    if ((tid & 31) == 0) { sred[0][tid >> 5] = s; sred[1][tid >> 5] = s2; }
    __syncthreads();
    if (tid < 32) {
        float a = (tid < 8) ? sred[0][tid] : 0.f;
        float b2 = (tid < 8) ? sred[1][tid] : 0.f;
#pragma unroll
        for (int o = 4; o; o >>= 1) {
            a  += __shfl_xor_sync(0xffffffffu, a,  o);
            b2 += __shfl_xor_sync(0xffffffffu, b2, o);
        }
        if (tid == 0) { sred[0][0] = a; sred[1][0] = b2; }
    }
    __syncthreads();
    const float mean = sred[0][0] * (1.f / 1024.f);
    const float var  = sred[1][0] * (1.f / 1024.f) - mean * mean;
    const float inv  = rsqrtf(var + 1e-5f);
#pragma unroll
    for (int t = 0; t < 4; ++t) {
        int c = tid + 256 * t;
        out[(size_t)row * HID + c] = (x[t] - mean) * inv * gamma[c] + beta[c];
    }
}

// ============================ launch ============================
extern "C" void kernel_launch(void* const* d_in, const int* in_sizes, int n_in,
                              void* d_out, int out_size)
{
    (void)in_sizes; (void)n_in; (void)out_size;
    const float* hs    = (const float*)d_in[0];
    const float* pos   = (const float*)d_in[1];
    const float* seg   = (const float*)d_in[2];
    const float* mask  = (const float*)d_in[3];
    const float* wq    = (const float*)d_in[4];
    const float* wk    = (const float*)d_in[5];
    const float* wv    = (const float*)d_in[6];
    const float* wr    = (const float*)d_in[7];
    const float* wo    = (const float*)d_in[8];
    const float* rwb   = (const float*)d_in[9];
    const float* rrb   = (const float*)d_in[10];
    const float* rsb   = (const float*)d_in[11];
    const float* segm  = (const float*)d_in[12];
    const float* gamma = (const float*)d_in[13];
    const float* beta  = (const float*)d_in[14];
    float* out = (float*)d_out;

    float *QKVd, *KRd, *PRd, *EF1d, *BWd, *BRd;
    cudaGetSymbolAddress((void**)&QKVd, g_QKV);
    cudaGetSymbolAddress((void**)&KRd, g_KR);
    cudaGetSymbolAddress((void**)&PRd, g_PR);
    cudaGetSymbolAddress((void**)&EF1d, g_EF1);
    cudaGetSymbolAddress((void**)&BWd, g_BW);
    cudaGetSymbolAddress((void**)&BRd, g_BR);

    __nv_bfloat16 *HA0, *HA1, *PA0, *PA1, *AOs0, *AOs1, *WB0, *WB1;
    __nv_bfloat16 *QKVs0, *QKVs1, *KRs0, *KRs1;
    cudaGetSymbolAddress((void**)&HA0, g_HA0);
    cudaGetSymbolAddress((void**)&HA1, g_HA1);
    cudaGetSymbolAddress((void**)&PA0, g_PA0);
    cudaGetSymbolAddress((void**)&PA1, g_PA1);
    cudaGetSymbolAddress((void**)&AOs0, g_AOs0);
    cudaGetSymbolAddress((void**)&AOs1, g_AOs1);
    cudaGetSymbolAddress((void**)&WB0, g_WB0);
    cudaGetSymbolAddress((void**)&WB1, g_WB1);
    cudaGetSymbolAddress((void**)&QKVs0, g_QKVs0);
    cudaGetSymbolAddress((void**)&QKVs1, g_QKVs1);
    cudaGetSymbolAddress((void**)&KRs0, g_KRs0);
    cudaGetSymbolAddress((void**)&KRs1, g_KRs1);

    cudaFuncSetAttribute(gemm_mma, cudaFuncAttributeMaxDynamicSharedMemorySize, GEMM_SMEM);
    cudaFuncSetAttribute(attn_kernel, cudaFuncAttributeMaxDynamicSharedMemorySize, ATTN_SMEM);

    const size_t WSZ = (size_t)HID * HID;

    // Splits (inputs + weights)
    split2_kernel<<<(IB*HID/4 + 255)/256, 256>>>(hs,  HA0, HA1, IB*HID/4);
    split2_kernel<<<(JBR*HID/4 + 255)/256, 256>>>(pos, PA0, PA1, JBR*HID/4);
    dim3 gt(32, 32), bt(32, 8);
    tsplit2_kernel<<<gt, bt>>>(wq, WB0 + 0*WSZ, WB1 + 0*WSZ);
    tsplit2_kernel<<<gt, bt>>>(wk, WB0 + 1*WSZ, WB1 + 1*WSZ);
    tsplit2_kernel<<<gt, bt>>>(wv, WB0 + 2*WSZ, WB1 + 2*WSZ);
    tsplit2_kernel<<<gt, bt>>>(wr, WB0 + 3*WSZ, WB1 + 3*WSZ);
    split2_kernel<<<(HID*HID/4 + 255)/256, 256>>>(wo, WB0 + 4*WSZ, WB1 + 4*WSZ, HID*HID/4);

    // Fused QKV projection (N = 3072) + KR projection
    dim3 gqkv(QKVW / 128, IB / 128);   // (24, 32)
    gemm_mma<<<gqkv, 256, GEMM_SMEM>>>(HA0, HA1, WB0, WB1, QKVd, IB, QKVW, HID);
    dim3 gr(8, 64);
    gemm_mma<<<gr, 256, GEMM_SMEM>>>(PA0, PA1, WB0+3*WSZ, WB1+3*WSZ, KRd, JBR, HID, HID);

    // Pre-split activations for attention (pure-copy loads in attn)
    split2_kernel<<<(IB*QKVW/4 + 255)/256, 256>>>(QKVd, QKVs0, QKVs1, IB*QKVW/4);
    split2_kernel<<<(JBR*HID/4 + 255)/256, 256>>>(KRd, KRs0, KRs1, JBR*HID/4);

    // Bias precomputes
    ef1_kernel    <<<IB * NH / 4, 128>>>(QKVd, rsb, segm, EF1d);
    rowbias_kernel<<<QL * BSZ * NH / 4, 128>>>(QKVd, QKVW, 1024, rwb, BWd, QL);
    rowbias_kernel<<<PL * BSZ * NH / 4, 128>>>(KRd,  HID,  0,    rrb, BRd, PL);

    // Fused flash attention (bf16 presplit loads; writes bf16 AO splits)
    dim3 ga(QL / 64, BNH);             // (8, 128)
    attn_kernel<<<ga, 256, ATTN_SMEM>>>(QKVd, QKVs0, QKVs1, KRs0, KRs1,
                                        EF1d, BWd, BRd, seg, mask, AOs0, AOs1);

    // Output projection (HMMA) + LN
    dim3 go(8, 32);
    gemm_mma<<<go, 256, GEMM_SMEM>>>(AOs0, AOs1, WB0+4*WSZ, WB1+4*WSZ, PRd, IB, HID, HID);
    ln_kernel<<<IB, 256>>>(PRd, hs, gamma, beta, out);
}